// round 10
// baseline (speedup 1.0000x reference)
#include <cuda_runtime.h>
#include <cstdint>

// Problem constants (B=4,H=8,S=1024,D=64)
#define BH 32
#define S 1024
#define D 64
#define N_ELE (BH * S * S)          // 33554432 = 2^25
#define SHIFT 9                     // PINNED: SHIFT=12 causes atomic contention collapse
#define NB (1u << (31 - SHIFT))     // 4M buckets
#define QPITCH 129                  // qk 128-wide tile pitch (mod 32 == 1)
#define HBLK 4096                   // histogram scan chunks (1024 buckets each)
#define AVP 65                      // av smem pitch

// Static device scratch (allocation-free rule: __device__ globals only)
__device__ float    g_score[N_ELE];      // signed cosine scores, row-major [BH*S, S]
__device__ unsigned g_hist[NB];          // bucket populations
__device__ unsigned g_partial[HBLK];     // per-chunk population sums
__device__ float    g_wmag[NB];          // per-bucket weight magnitude
__device__ float    g_invq[BH * S];
__device__ float    g_invk[BH * S];

// ---------------------------------------------------------------------------
// Stage 1: inverse lengths (one warp per row) + fused histogram zeroing
// ---------------------------------------------------------------------------
__global__ void norms_zero_kernel(const float* __restrict__ q,
                                  const float* __restrict__ k) {
    unsigned gid = blockIdx.x * blockDim.x + threadIdx.x;
    if (gid < NB / 4)
        reinterpret_cast<uint4*>(g_hist)[gid] = make_uint4(0u, 0u, 0u, 0u);

    int warp = gid >> 5;
    int lane = threadIdx.x & 31;
    if (warp >= 2 * BH * S) return;
    bool is_q = warp < BH * S;
    int row = is_q ? warp : warp - BH * S;
    const float* p = (is_q ? q : k) + (size_t)row * D;
    float v0 = p[lane], v1 = p[lane + 32];
    float s = v0 * v0 + v1 * v1;
    #pragma unroll
    for (int o = 16; o; o >>= 1) s += __shfl_xor_sync(0xffffffffu, s, o);
    if (lane == 0) (is_q ? g_invq : g_invk)[row] = 1.0f / (sqrtf(s) + 1e-5f);
}

// ---------------------------------------------------------------------------
// Stage 2: QK^T (fp32) -> signed scores (STG.128) + atomic bucket histogram
// 128x128 tile, 256 threads, 8x8 micro-tile (proven core, unchanged)
// ---------------------------------------------------------------------------
__global__ void qk_kernel(const float* __restrict__ Q, const float* __restrict__ K) {
    extern __shared__ float sm[];
    float* Qs = sm;                    // [64][QPITCH]  Qs[d][r]
    float* Ks = sm + 64 * QPITCH;      // [64][QPITCH]  Ks[d][c]
    int bh = blockIdx.z;
    int i0 = blockIdx.y * 128;
    int j0 = blockIdx.x * 128;
    const float* Qb = Q + ((size_t)bh * S + i0) * D;
    const float* Kb = K + ((size_t)bh * S + j0) * D;
    int tid = threadIdx.x;

    #pragma unroll
    for (int l = 0; l < 32; l++) {
        int idx = tid + l * 256;          // 0..8191
        int r = idx >> 6, d = idx & 63;
        Qs[d * QPITCH + r] = Qb[(size_t)r * D + d];
        Ks[d * QPITCH + r] = Kb[(size_t)r * D + d];
    }
    __syncthreads();

    int tx = tid & 15, ty = tid >> 4;     // 16x16 threads, 8x8 each
    float acc[8][8] = {};
    #pragma unroll 8
    for (int d = 0; d < 64; d++) {
        float a[8], b[8];
        const float* Qrow = &Qs[d * QPITCH + ty * 8];
        const float* Krow = &Ks[d * QPITCH + tx * 8];
        #pragma unroll
        for (int u = 0; u < 8; u++) a[u] = Qrow[u];
        #pragma unroll
        for (int u = 0; u < 8; u++) b[u] = Krow[u];
        #pragma unroll
        for (int r = 0; r < 8; r++)
            #pragma unroll
            for (int u = 0; u < 8; u++)
                acc[r][u] += a[r] * b[u];
    }

    float iq[8], ik[8];
    #pragma unroll
    for (int u = 0; u < 8; u++) {
        iq[u] = g_invq[bh * S + i0 + ty * 8 + u];
        ik[u] = g_invk[bh * S + j0 + tx * 8 + u];
    }
    #pragma unroll
    for (int r = 0; r < 8; r++) {
        unsigned row = (unsigned)(bh * S + i0 + ty * 8 + r);
        float s[8];
        #pragma unroll
        for (int u = 0; u < 8; u++) s[u] = acc[r][u] * iq[r] * ik[u];
        unsigned base = (row << 10) | (unsigned)(j0 + tx * 8);
        *reinterpret_cast<float4*>(&g_score[base]) =
            make_float4(s[0], s[1], s[2], s[3]);
        *reinterpret_cast<float4*>(&g_score[base + 4]) =
            make_float4(s[4], s[5], s[6], s[7]);
        #pragma unroll
        for (int u = 0; u < 8; u++) {
            unsigned key = __float_as_uint(s[u]) & 0x7fffffffu;
            atomicAdd(&g_hist[key >> SHIFT], 1u);
        }
    }
}

// ---------------------------------------------------------------------------
// Stage 3a: per-chunk population sums (HBLK chunks of 1024 buckets)
// ---------------------------------------------------------------------------
__global__ void hist_sum_kernel() {
    __shared__ unsigned red[256];
    unsigned t = threadIdx.x, b = blockIdx.x;
    uint4 h = reinterpret_cast<const uint4*>(g_hist)[b * 256 + t];
    red[t] = h.x + h.y + h.z + h.w;
    __syncthreads();
    #pragma unroll
    for (int o = 128; o; o >>= 1) {
        if (t < (unsigned)o) red[t] += red[t + o];
        __syncthreads();
    }
    if (t == 0) g_partial[b] = red[0];
}

// ---------------------------------------------------------------------------
// Stage 3b: per-chunk offset + intra-chunk scan + wmag, one pass
// ---------------------------------------------------------------------------
__global__ void scan_wmag_kernel() {
    __shared__ unsigned red[256];
    __shared__ unsigned sscan[256];
    unsigned t = threadIdx.x, b = blockIdx.x;

    unsigned s = 0;
    for (unsigned i = t; i < b; i += 256) s += g_partial[i];
    red[t] = s;
    __syncthreads();
    #pragma unroll
    for (int o = 128; o; o >>= 1) {
        if (t < (unsigned)o) red[t] += red[t + o];
        __syncthreads();
    }
    unsigned blockoff = red[0];
    __syncthreads();

    uint4 h = reinterpret_cast<const uint4*>(g_hist)[b * 256 + t];
    unsigned s4 = h.x + h.y + h.z + h.w;
    unsigned v = s4;
    sscan[t] = v;
    __syncthreads();
    #pragma unroll
    for (int o = 1; o < 256; o <<= 1) {
        unsigned add = (t >= (unsigned)o) ? sscan[t - o] : 0u;
        __syncthreads();
        v += add;
        sscan[t] = v;
        __syncthreads();
    }
    unsigned excl = blockoff + v - s4;

    unsigned pops[4] = {h.x, h.y, h.z, h.w};
    unsigned cums[4] = {excl, excl + h.x, excl + h.x + h.y,
                        excl + h.x + h.y + h.z};
    const float inv = 1.0f / (float)(N_ELE - 1);
    float w[4];
    #pragma unroll
    for (int u = 0; u < 4; u++) {
        if (pops[u] == 0u) { w[u] = 0.0f; continue; }
        float rmid = (float)cums[u] + 0.5f * (float)(pops[u] - 1u);
        w[u] = -logf(fmaf(rmid, inv, 0x1p-25f));
    }
    reinterpret_cast<float4*>(g_wmag)[b * 256 + t] =
        make_float4(w[0], w[1], w[2], w[3]);
}

// ---------------------------------------------------------------------------
// Stage 4 (fused): out = (W / rowsum(|W|)) @ V
// W materialized on the fly: w = sign(score)*wmag[bucket(|score|)].
// Software-pipelined, double-buffered smem: next tile's score/V loads are
// issued before the GEMM first half; wmag gathers between halves.
// 64x64 tile, 256 threads, 4x4 micro.
// ---------------------------------------------------------------------------
__global__ void __launch_bounds__(256)
av_kernel(const float* __restrict__ V, float* __restrict__ out) {
    extern __shared__ float sm[];
    // layout: Ws0 Ws1 Vs0 Vs1 rsum
    float* WsB[2] = {sm, sm + 64 * AVP};
    float* VsB[2] = {sm + 2 * 64 * AVP, sm + 3 * 64 * AVP};
    float* rsum = sm + 4 * 64 * AVP;
    int bh = blockIdx.y;
    int i0 = blockIdx.x * 64;
    int tid = threadIdx.x, tx = tid & 15, ty = tid >> 4;
    const float* Wb = g_score + ((size_t)(bh * S + i0)) * S;
    const float* Vb = V + (size_t)bh * S * D;

    int sr = tid >> 4;          // staging: 16 rows per pass? No: idx mapping below
    (void)sr;

    // ---- prologue: stage tile 0 into buffer 0 ----
    float sc[16], vv[16];
    #pragma unroll
    for (int l = 0; l < 16; l++) {
        int idx = tid + l * 256;
        int r = idx >> 6, c = idx & 63;
        sc[l] = Wb[(size_t)r * S + c];
        vv[l] = Vb[(size_t)r * D + c];
    }
    float wv[16];
    #pragma unroll
    for (int l = 0; l < 16; l++) {
        unsigned key = __float_as_uint(sc[l]) & 0x7fffffffu;
        wv[l] = (key == 0u) ? 0.0f
                            : copysignf(__ldg(&g_wmag[key >> SHIFT]), sc[l]);
    }
    #pragma unroll
    for (int l = 0; l < 16; l++) {
        int idx = tid + l * 256;
        int r = idx >> 6, c = idx & 63;
        WsB[0][r * AVP + c] = wv[l];
        VsB[0][r * AVP + c] = vv[l];
    }
    __syncthreads();

    float acc[4][4] = {};
    float rs[4] = {};
    for (int kt = 0; kt < 16; kt++) {
        float* Ws = WsB[kt & 1];
        float* Vs = VsB[kt & 1];
        float* Wn = WsB[(kt + 1) & 1];
        float* Vn = VsB[(kt + 1) & 1];
        bool more = (kt < 15);

        // (a) issue next tile's global loads (independent, high MLP)
        if (more) {
            int koff = (kt + 1) * 64;
            #pragma unroll
            for (int l = 0; l < 16; l++) {
                int idx = tid + l * 256;
                int r = idx >> 6, c = idx & 63;
                sc[l] = Wb[(size_t)r * S + koff + c];
                vv[l] = Vb[(size_t)(koff + r) * D + c];
            }
        }

        // (b) GEMM first half — hides the score/V loads
        #pragma unroll 8
        for (int kk = 0; kk < 32; kk++) {
            float a[4], b[4];
            #pragma unroll
            for (int u = 0; u < 4; u++) b[u] = Vs[kk * AVP + tx * 4 + u];
            #pragma unroll
            for (int r = 0; r < 4; r++) a[r] = Ws[(ty * 4 + r) * AVP + kk];
            if (tx == 0) {
                #pragma unroll
                for (int r = 0; r < 4; r++) rs[r] += fabsf(a[r]);
            }
            #pragma unroll
            for (int r = 0; r < 4; r++)
                #pragma unroll
                for (int u = 0; u < 4; u++)
                    acc[r][u] += a[r] * b[u];
        }

        // (c) issue the independent wmag gathers for the next tile
        if (more) {
            #pragma unroll
            for (int l = 0; l < 16; l++) {
                unsigned key = __float_as_uint(sc[l]) & 0x7fffffffu;
                wv[l] = (key == 0u) ? 0.0f
                                    : copysignf(__ldg(&g_wmag[key >> SHIFT]), sc[l]);
            }
        }

        // (d) GEMM second half — hides the gathers
        #pragma unroll 8
        for (int kk = 32; kk < 64; kk++) {
            float a[4], b[4];
            #pragma unroll
            for (int u = 0; u < 4; u++) b[u] = Vs[kk * AVP + tx * 4 + u];
            #pragma unroll
            for (int r = 0; r < 4; r++) a[r] = Ws[(ty * 4 + r) * AVP + kk];
            if (tx == 0) {
                #pragma unroll
                for (int r = 0; r < 4; r++) rs[r] += fabsf(a[r]);
            }
            #pragma unroll
            for (int r = 0; r < 4; r++)
                #pragma unroll
                for (int u = 0; u < 4; u++)
                    acc[r][u] += a[r] * b[u];
        }

        // (e) store next tile into the other buffer
        if (more) {
            #pragma unroll
            for (int l = 0; l < 16; l++) {
                int idx = tid + l * 256;
                int r = idx >> 6, c = idx & 63;
                Wn[r * AVP + c] = wv[l];
                Vn[r * AVP + c] = vv[l];
            }
        }
        __syncthreads();
    }

    if (tx == 0) {
        #pragma unroll
        for (int r = 0; r < 4; r++) rsum[ty * 4 + r] = rs[r];
    }
    __syncthreads();
    #pragma unroll
    for (int r = 0; r < 4; r++) {
        float inv = 1.0f / rsum[ty * 4 + r];
        size_t obase = ((size_t)(bh * S) + i0 + ty * 4 + r) * D + tx * 4;
        #pragma unroll
        for (int u = 0; u < 4; u++)
            out[obase + u] = acc[r][u] * inv;
    }
}

// ---------------------------------------------------------------------------
extern "C" void kernel_launch(void* const* d_in, const int* in_sizes, int n_in,
                              void* d_out, int out_size) {
    const float* q = (const float*)d_in[0];
    const float* k = (const float*)d_in[1];
    const float* v = (const float*)d_in[2];
    float* out = (float*)d_out;

    // Stage 1: inverse lengths + zero histogram (fused)
    norms_zero_kernel<<<8192, 256>>>(q, k);

    // Stage 2: cosine scores + bucket histogram (128x128 tiles, 66KB dyn smem)
    const int qk_smem = 2 * 64 * QPITCH * sizeof(float);
    cudaFuncSetAttribute(qk_kernel, cudaFuncAttributeMaxDynamicSharedMemorySize,
                         qk_smem);
    dim3 g1(S / 128, S / 128, BH);
    qk_kernel<<<g1, 256, qk_smem>>>(q, k);

    // Stage 3: custom scan + wmag
    hist_sum_kernel<<<HBLK, 256>>>();
    scan_wmag_kernel<<<HBLK, 256>>>();

    // Stage 4 (fused): weights + row-L1-normalize + apply to V
    const int av_smem = (4 * 64 * AVP + 64) * sizeof(float);
    cudaFuncSetAttribute(av_kernel, cudaFuncAttributeMaxDynamicSharedMemorySize,
                         av_smem);
    dim3 g2(S / 64, BH);
    av_kernel<<<g2, 256, av_smem>>>(v, out);
}

// round 11
// speedup vs baseline: 1.2964x; 1.2964x over previous
#include <cuda_runtime.h>
#include <cstdint>

// Problem constants (B=4,H=8,S=1024,D=64)
#define BH 32
#define S 1024
#define D 64
#define N_ELE (BH * S * S)          // 33554432 = 2^25
#define SHIFT 9                     // PINNED: SHIFT=12 causes atomic contention collapse
#define NB (1u << (31 - SHIFT))     // 4M buckets
#define QPITCH 129                  // qk 128-wide tile pitch (mod 32 == 1)
#define HBLK 4096                   // histogram scan chunks (1024 buckets each)
#define AVP 68                      // av smem pitch (16B-aligned rows)

// Static device scratch (allocation-free rule: __device__ globals only)
__device__ float    g_score[N_ELE];      // signed cosine scores, row-major [BH*S, S]
__device__ float    g_w[N_ELE];          // final weights
__device__ unsigned g_hist[NB];          // bucket populations
__device__ unsigned g_partial[HBLK];     // per-chunk population sums
__device__ float    g_wmag[NB];          // per-bucket weight magnitude
__device__ float    g_invr[BH * S];      // 1 / rowsum(|w|)
__device__ float    g_invq[BH * S];
__device__ float    g_invk[BH * S];

// ---------------------------------------------------------------------------
// Stage 1: inverse lengths (one warp per row) + fused histogram zeroing
// ---------------------------------------------------------------------------
__global__ void norms_zero_kernel(const float* __restrict__ q,
                                  const float* __restrict__ k) {
    unsigned gid = blockIdx.x * blockDim.x + threadIdx.x;
    if (gid < NB / 4)
        reinterpret_cast<uint4*>(g_hist)[gid] = make_uint4(0u, 0u, 0u, 0u);

    int warp = gid >> 5;
    int lane = threadIdx.x & 31;
    if (warp >= 2 * BH * S) return;
    bool is_q = warp < BH * S;
    int row = is_q ? warp : warp - BH * S;
    const float* p = (is_q ? q : k) + (size_t)row * D;
    float v0 = p[lane], v1 = p[lane + 32];
    float s = v0 * v0 + v1 * v1;
    #pragma unroll
    for (int o = 16; o; o >>= 1) s += __shfl_xor_sync(0xffffffffu, s, o);
    if (lane == 0) (is_q ? g_invq : g_invk)[row] = 1.0f / (sqrtf(s) + 1e-5f);
}

// ---------------------------------------------------------------------------
// Stage 2: QK^T (fp32) -> signed scores (STG.128) + atomic bucket histogram
// 128x128 tile, 256 threads, 8x8 micro-tile (proven core, unchanged)
// ---------------------------------------------------------------------------
__global__ void qk_kernel(const float* __restrict__ Q, const float* __restrict__ K) {
    extern __shared__ float sm[];
    float* Qs = sm;                    // [64][QPITCH]  Qs[d][r]
    float* Ks = sm + 64 * QPITCH;      // [64][QPITCH]  Ks[d][c]
    int bh = blockIdx.z;
    int i0 = blockIdx.y * 128;
    int j0 = blockIdx.x * 128;
    const float* Qb = Q + ((size_t)bh * S + i0) * D;
    const float* Kb = K + ((size_t)bh * S + j0) * D;
    int tid = threadIdx.x;

    #pragma unroll
    for (int l = 0; l < 32; l++) {
        int idx = tid + l * 256;          // 0..8191
        int r = idx >> 6, d = idx & 63;
        Qs[d * QPITCH + r] = Qb[(size_t)r * D + d];
        Ks[d * QPITCH + r] = Kb[(size_t)r * D + d];
    }
    __syncthreads();

    int tx = tid & 15, ty = tid >> 4;     // 16x16 threads, 8x8 each
    float acc[8][8] = {};
    #pragma unroll 8
    for (int d = 0; d < 64; d++) {
        float a[8], b[8];
        const float* Qrow = &Qs[d * QPITCH + ty * 8];
        const float* Krow = &Ks[d * QPITCH + tx * 8];
        #pragma unroll
        for (int u = 0; u < 8; u++) a[u] = Qrow[u];
        #pragma unroll
        for (int u = 0; u < 8; u++) b[u] = Krow[u];
        #pragma unroll
        for (int r = 0; r < 8; r++)
            #pragma unroll
            for (int u = 0; u < 8; u++)
                acc[r][u] += a[r] * b[u];
    }

    float iq[8], ik[8];
    #pragma unroll
    for (int u = 0; u < 8; u++) {
        iq[u] = g_invq[bh * S + i0 + ty * 8 + u];
        ik[u] = g_invk[bh * S + j0 + tx * 8 + u];
    }
    #pragma unroll
    for (int r = 0; r < 8; r++) {
        unsigned row = (unsigned)(bh * S + i0 + ty * 8 + r);
        float s[8];
        #pragma unroll
        for (int u = 0; u < 8; u++) s[u] = acc[r][u] * iq[r] * ik[u];
        unsigned base = (row << 10) | (unsigned)(j0 + tx * 8);
        *reinterpret_cast<float4*>(&g_score[base]) =
            make_float4(s[0], s[1], s[2], s[3]);
        *reinterpret_cast<float4*>(&g_score[base + 4]) =
            make_float4(s[4], s[5], s[6], s[7]);
        #pragma unroll
        for (int u = 0; u < 8; u++) {
            unsigned key = __float_as_uint(s[u]) & 0x7fffffffu;
            atomicAdd(&g_hist[key >> SHIFT], 1u);
        }
    }
}

// ---------------------------------------------------------------------------
// Stage 3a: per-chunk population sums (HBLK chunks of 1024 buckets)
// ---------------------------------------------------------------------------
__global__ void hist_sum_kernel() {
    __shared__ unsigned red[256];
    unsigned t = threadIdx.x, b = blockIdx.x;
    uint4 h = reinterpret_cast<const uint4*>(g_hist)[b * 256 + t];
    red[t] = h.x + h.y + h.z + h.w;
    __syncthreads();
    #pragma unroll
    for (int o = 128; o; o >>= 1) {
        if (t < (unsigned)o) red[t] += red[t + o];
        __syncthreads();
    }
    if (t == 0) g_partial[b] = red[0];
}

// ---------------------------------------------------------------------------
// Stage 3b: per-chunk offset + intra-chunk scan + wmag, one pass
// ---------------------------------------------------------------------------
__global__ void scan_wmag_kernel() {
    __shared__ unsigned red[256];
    __shared__ unsigned sscan[256];
    unsigned t = threadIdx.x, b = blockIdx.x;

    unsigned s = 0;
    for (unsigned i = t; i < b; i += 256) s += g_partial[i];
    red[t] = s;
    __syncthreads();
    #pragma unroll
    for (int o = 128; o; o >>= 1) {
        if (t < (unsigned)o) red[t] += red[t + o];
        __syncthreads();
    }
    unsigned blockoff = red[0];
    __syncthreads();

    uint4 h = reinterpret_cast<const uint4*>(g_hist)[b * 256 + t];
    unsigned s4 = h.x + h.y + h.z + h.w;
    unsigned v = s4;
    sscan[t] = v;
    __syncthreads();
    #pragma unroll
    for (int o = 1; o < 256; o <<= 1) {
        unsigned add = (t >= (unsigned)o) ? sscan[t - o] : 0u;
        __syncthreads();
        v += add;
        sscan[t] = v;
        __syncthreads();
    }
    unsigned excl = blockoff + v - s4;

    unsigned pops[4] = {h.x, h.y, h.z, h.w};
    unsigned cums[4] = {excl, excl + h.x, excl + h.x + h.y,
                        excl + h.x + h.y + h.z};
    const float inv = 1.0f / (float)(N_ELE - 1);
    float w[4];
    #pragma unroll
    for (int u = 0; u < 4; u++) {
        if (pops[u] == 0u) { w[u] = 0.0f; continue; }
        float rmid = (float)cums[u] + 0.5f * (float)(pops[u] - 1u);
        w[u] = -logf(fmaf(rmid, inv, 0x1p-25f));
    }
    reinterpret_cast<float4*>(g_wmag)[b * 256 + t] =
        make_float4(w[0], w[1], w[2], w[3]);
}

// ---------------------------------------------------------------------------
// Stage 4: elementwise weights + per-row L1 sums
// One block per score row (1024 elems, 256 threads x float4).
// w = sign(score)*wmag[bucket(|score|)];  g_invr[row] = 1/sum(|w|)
// ---------------------------------------------------------------------------
__global__ void weight_kernel() {
    __shared__ float red[256];
    unsigned row = blockIdx.x;
    unsigned t = threadIdx.x;
    unsigned i = row * (unsigned)S + t * 4u;
    float4 s4 = *reinterpret_cast<const float4*>(&g_score[i]);
    float sv[4] = {s4.x, s4.y, s4.z, s4.w};
    float w[4];
    float asum = 0.0f;
    #pragma unroll
    for (int u = 0; u < 4; u++) {
        unsigned key = __float_as_uint(sv[u]) & 0x7fffffffu;
        float m = (key == 0u) ? 0.0f : __ldg(&g_wmag[key >> SHIFT]);
        asum += m;
        w[u] = copysignf(m, sv[u]);
    }
    *reinterpret_cast<float4*>(&g_w[i]) = make_float4(w[0], w[1], w[2], w[3]);

    red[t] = asum;
    __syncthreads();
    #pragma unroll
    for (int o = 128; o >= 32; o >>= 1) {
        if (t < (unsigned)o) red[t] += red[t + o];
        __syncthreads();
    }
    if (t < 32) {
        float v = red[t] + red[t + 32];
        // careful: red[t]+red[t+32] double-counts at o=32 — use clean warp path
        v = red[t];
        #pragma unroll
        for (int o = 16; o; o >>= 1) v += __shfl_xor_sync(0xffffffffu, v, o);
        if (t == 0) g_invr[row] = 1.0f / v;
    }
}

// ---------------------------------------------------------------------------
// Stage 5: out[i,:] = g_invr[i] * (W[i,:] @ V)
// 64x64 tile, 256 threads, 4x4 micro; pitch-68 smem, LDS.128 V-operand,
// float4 staging and output. No rowsum logic in the hot loop.
// ---------------------------------------------------------------------------
__global__ void av_kernel(const float* __restrict__ V, float* __restrict__ out) {
    __shared__ float Ws[64][AVP];   // Ws[r][kk]
    __shared__ float Vs[64][AVP];   // Vs[kk][c]
    int bh = blockIdx.y;
    int i0 = blockIdx.x * 64;
    int tid = threadIdx.x, tx = tid & 15, ty = tid >> 4;
    const float* Wb = g_w + ((size_t)(bh * S + i0)) * S;
    const float* Vb = V + (size_t)bh * S * D;

    float acc[4][4] = {};
    for (int kt = 0; kt < S; kt += 64) {
        #pragma unroll
        for (int l = 0; l < 4; l++) {
            int idx = tid + l * 256;           // 0..1023 float4 slots
            int r = idx >> 4, c = (idx & 15) * 4;
            *reinterpret_cast<float4*>(&Ws[r][c]) =
                *reinterpret_cast<const float4*>(&Wb[(size_t)r * S + kt + c]);
            *reinterpret_cast<float4*>(&Vs[r][c]) =
                *reinterpret_cast<const float4*>(&Vb[(size_t)(kt + r) * D + c]);
        }
        __syncthreads();
        #pragma unroll 8
        for (int kk = 0; kk < 64; kk++) {
            float4 b4 = *reinterpret_cast<const float4*>(&Vs[kk][tx * 4]);
            float b[4] = {b4.x, b4.y, b4.z, b4.w};
            float a[4];
            #pragma unroll
            for (int r = 0; r < 4; r++) a[r] = Ws[ty * 4 + r][kk];
            #pragma unroll
            for (int r = 0; r < 4; r++)
                #pragma unroll
                for (int u = 0; u < 4; u++)
                    acc[r][u] += a[r] * b[u];
        }
        __syncthreads();
    }
    #pragma unroll
    for (int r = 0; r < 4; r++) {
        int row = bh * S + i0 + ty * 4 + r;
        float inv = g_invr[row];
        *reinterpret_cast<float4*>(&out[(size_t)row * D + tx * 4]) =
            make_float4(acc[r][0] * inv, acc[r][1] * inv,
                        acc[r][2] * inv, acc[r][3] * inv);
    }
}

// ---------------------------------------------------------------------------
extern "C" void kernel_launch(void* const* d_in, const int* in_sizes, int n_in,
                              void* d_out, int out_size) {
    const float* q = (const float*)d_in[0];
    const float* k = (const float*)d_in[1];
    const float* v = (const float*)d_in[2];
    float* out = (float*)d_out;

    // Stage 1: inverse lengths + zero histogram (fused)
    norms_zero_kernel<<<8192, 256>>>(q, k);

    // Stage 2: cosine scores + bucket histogram (128x128 tiles, 66KB dyn smem)
    const int qk_smem = 2 * 64 * QPITCH * sizeof(float);
    cudaFuncSetAttribute(qk_kernel, cudaFuncAttributeMaxDynamicSharedMemorySize,
                         qk_smem);
    dim3 g1(S / 128, S / 128, BH);
    qk_kernel<<<g1, 256, qk_smem>>>(q, k);

    // Stage 3: custom scan + wmag
    hist_sum_kernel<<<HBLK, 256>>>();
    scan_wmag_kernel<<<HBLK, 256>>>();

    // Stage 4: weights + per-row L1 sums (one block per row)
    weight_kernel<<<BH * S, 256>>>();

    // Stage 5: GEMM + scale by 1/rowsum
    dim3 g2(S / 64, BH);
    av_kernel<<<g2, 256>>>(v, out);
}